// round 5
// baseline (speedup 1.0000x reference)
#include <cuda_runtime.h>

// Problem constants
#define CAP_A   32
#define CAP_B   32
#define KK      3
#define PSIZE   16
#define STRIDE  2
#define OH      15
#define OW      15
#define NBATCH  2
#define NPOS    (NBATCH*OH*OW)   // 450
#define KKA     (KK*KK*CAP_A)    // 288
#define EPS_SQ  1e-8f
#define CPT     9                // capsules per thread (one warp per (n,j))
#define WPB     8                // warps (j values) per block
#define FULL    0xffffffffu

// Butterfly vector-exchange reduction: 32 lanes each hold t[0..15];
// afterwards lane l holds the lane-sum of component (l & 15).
__device__ __forceinline__ void vec_reduce16(float t[16], int lane) {
#pragma unroll
    for (int k = 0; k < 16; k++)
        t[k] += __shfl_xor_sync(FULL, t[k], 16);
    {
        const bool hi = lane & 8;
#pragma unroll
        for (int k = 0; k < 8; k++) {
            float keep = hi ? t[k + 8] : t[k];
            float send = hi ? t[k]     : t[k + 8];
            t[k] = keep + __shfl_xor_sync(FULL, send, 8);
        }
    }
    {
        const bool hi = lane & 4;
#pragma unroll
        for (int k = 0; k < 4; k++) {
            float keep = hi ? t[k + 4] : t[k];
            float send = hi ? t[k]     : t[k + 4];
            t[k] = keep + __shfl_xor_sync(FULL, send, 4);
        }
    }
    {
        const bool hi = lane & 2;
#pragma unroll
        for (int k = 0; k < 2; k++) {
            float keep = hi ? t[k + 2] : t[k];
            float send = hi ? t[k]     : t[k + 2];
            t[k] = keep + __shfl_xor_sync(FULL, send, 2);
        }
    }
    {
        const bool hi = lane & 1;
        float keep = hi ? t[1] : t[0];
        float send = hi ? t[0] : t[1];
        t[0] = keep + __shfl_xor_sync(FULL, send, 1);
    }
}

// Squash on the duplicated 16-vector (lanes l and l+16 both hold comp l&15).
__device__ __forceinline__ float squash16(float s) {
    float n2 = s * s;
#pragma unroll
    for (int off = 8; off >= 1; off >>= 1)
        n2 += __shfl_xor_sync(FULL, n2, off);
    return s * (n2 / (1.f + n2) * rsqrtf(n2 + EPS_SQ));
}

__global__ __launch_bounds__(WPB * 32) void caps_warp_kernel(
    const float* __restrict__ x,     // (2, 32, 32, 512)
    const float* __restrict__ w,     // (288, 32, 4, 4)
    float* __restrict__ out)         // (2, 15, 15, 512)
{
    const int bid = blockIdx.x;
    const int jg  = bid & 3;               // j group
    const int n   = bid >> 2;              // position index (same for all warps)
    const int b   = n / (OH * OW);
    const int rem = n % (OH * OW);
    const int oy  = rem / OW;
    const int ox  = rem % OW;

    const int lane = threadIdx.x & 31;     // = a (input capsule type)
    const int wid  = threadIdx.x >> 5;     // warp in block
    const int j    = jg * WPB + wid;       // output capsule for this warp

    // Thread owns i_c = c*32 + lane, c = ky*3 + kx.
    const float* xbase = x + ((size_t)((b * 32 + oy * STRIDE) * 32
                                       + ox * STRIDE) * 512 + lane * PSIZE);
    const float* wbase = w + ((size_t)(lane * CAP_B) + j) * PSIZE;

    float v[CPT][16];
#pragma unroll
    for (int c = 0; c < CPT; c++) {
        const int ky = c / 3, kx = c % 3;
        const float* xp = xbase + (size_t)(ky * 32 + kx) * 512;
        const float* wp = wbase + (size_t)c * 32 * CAP_B * PSIZE;
        float xm[16], wm[16];
#pragma unroll
        for (int t4 = 0; t4 < 4; t4++) {
            reinterpret_cast<float4*>(xm)[t4] = reinterpret_cast<const float4*>(xp)[t4];
            reinterpret_cast<float4*>(wm)[t4] = reinterpret_cast<const float4*>(wp)[t4];
        }
#pragma unroll
        for (int p = 0; p < 4; p++)
#pragma unroll
            for (int q = 0; q < 4; q++) {
                float acc = 0.f;
#pragma unroll
                for (int r = 0; r < 4; r++)
                    acc = fmaf(xm[p * 4 + r], wm[r * 4 + q], acc);
                v[c][p * 4 + q] = acc;
            }
    }

    float logit[CPT];
#pragma unroll
    for (int c = 0; c < CPT; c++) logit[c] = 0.f;

    float t[16];
    float pval;   // component (lane&15) of current p

    // ---- iteration 0: logits all zero -> r = 1/288 exactly ----
#pragma unroll
    for (int q = 0; q < 16; q++) {
        float s = v[0][q];
#pragma unroll
        for (int c = 1; c < CPT; c++) s += v[c][q];
        t[q] = s;
    }
    vec_reduce16(t, lane);
    pval = squash16(t[0] * (1.0f / (float)KKA));

    // agreement: logit_c += v_c . p  (p broadcast via inline shuffles)
#pragma unroll
    for (int q = 0; q < 16; q++) {
        const float pq = __shfl_sync(FULL, pval, q);
#pragma unroll
        for (int c = 0; c < CPT; c++)
            logit[c] = fmaf(v[c][q], pq, logit[c]);
    }

    // ---- iterations 1..2 ----
#pragma unroll
    for (int it = 1; it < 3; it++) {
        // softmax over all 288 logits (9 per thread, warp-reduced)
        float m = logit[0];
#pragma unroll
        for (int c = 1; c < CPT; c++) m = fmaxf(m, logit[c]);
#pragma unroll
        for (int off = 16; off >= 1; off >>= 1)
            m = fmaxf(m, __shfl_xor_sync(FULL, m, off));
        float e[CPT], z = 0.f;
#pragma unroll
        for (int c = 0; c < CPT; c++) { e[c] = __expf(logit[c] - m); z += e[c]; }
#pragma unroll
        for (int off = 16; off >= 1; off >>= 1)
            z += __shfl_xor_sync(FULL, z, off);
        const float rZ = __frcp_rn(z);

        // pool with weights e_c (scale by 1/Z after the reduction)
#pragma unroll
        for (int q = 0; q < 16; q++) {
            float s = e[0] * v[0][q];
#pragma unroll
            for (int c = 1; c < CPT; c++) s = fmaf(e[c], v[c][q], s);
            t[q] = s;
        }
        vec_reduce16(t, lane);
        pval = squash16(t[0] * rZ);

        if (it < 2) {
#pragma unroll
            for (int q = 0; q < 16; q++) {
                const float pq = __shfl_sync(FULL, pval, q);
#pragma unroll
                for (int c = 0; c < CPT; c++)
                    logit[c] = fmaf(v[c][q], pq, logit[c]);
            }
        }
    }

    // ---- output: lanes 0..15 hold p[0..15] ----
    if (lane < 16)
        out[(size_t)n * (CAP_B * PSIZE) + j * PSIZE + lane] = pval;
}

extern "C" void kernel_launch(void* const* d_in, const int* in_sizes, int n_in,
                              void* d_out, int out_size) {
    (void)in_sizes; (void)n_in; (void)out_size;
    const float* x = (const float*)d_in[0];
    const float* w = (const float*)d_in[1];
    float* out = (float*)d_out;

    dim3 grid(NPOS * (CAP_B / WPB));   // 1800 blocks: (n, j-group)
    dim3 block(WPB * 32);              // 256 threads, 8 warps
    caps_warp_kernel<<<grid, block>>>(x, w, out);
}

// round 6
// speedup vs baseline: 1.0569x; 1.0569x over previous
#include <cuda_runtime.h>
#include <cuda_fp16.h>

// Problem constants
#define CAP_A   32
#define CAP_B   32
#define KK      3
#define PSIZE   16
#define STRIDE  2
#define OH      15
#define OW      15
#define NBATCH  2
#define NPOS    (NBATCH*OH*OW)   // 450
#define KKA     (KK*KK*CAP_A)    // 288
#define EPS_SQ  1e-8f
#define CPT     9                // capsules per thread (one warp per (n,j))
#define FULL    0xffffffffu

// Butterfly vector-exchange reduction: 32 lanes each hold t[0..15];
// afterwards lane l holds the lane-sum of component (l & 15). 31 shuffles.
__device__ __forceinline__ void vec_reduce16(float t[16], int lane) {
#pragma unroll
    for (int k = 0; k < 16; k++)
        t[k] += __shfl_xor_sync(FULL, t[k], 16);
    {
        const bool hi = lane & 8;
#pragma unroll
        for (int k = 0; k < 8; k++) {
            float keep = hi ? t[k + 8] : t[k];
            float send = hi ? t[k]     : t[k + 8];
            t[k] = keep + __shfl_xor_sync(FULL, send, 8);
        }
    }
    {
        const bool hi = lane & 4;
#pragma unroll
        for (int k = 0; k < 4; k++) {
            float keep = hi ? t[k + 4] : t[k];
            float send = hi ? t[k]     : t[k + 4];
            t[k] = keep + __shfl_xor_sync(FULL, send, 4);
        }
    }
    {
        const bool hi = lane & 2;
#pragma unroll
        for (int k = 0; k < 2; k++) {
            float keep = hi ? t[k + 2] : t[k];
            float send = hi ? t[k]     : t[k + 2];
            t[k] = keep + __shfl_xor_sync(FULL, send, 2);
        }
    }
    {
        const bool hi = lane & 1;
        float keep = hi ? t[1] : t[0];
        float send = hi ? t[0] : t[1];
        t[0] = keep + __shfl_xor_sync(FULL, send, 1);
    }
}

// Squash on the duplicated 16-vector (lanes l and l+16 both hold comp l&15).
__device__ __forceinline__ float squash16(float s) {
    float n2 = s * s;
#pragma unroll
    for (int off = 8; off >= 1; off >>= 1)
        n2 += __shfl_xor_sync(FULL, n2, off);
    return s * (n2 / (1.f + n2) * rsqrtf(n2 + EPS_SQ));
}

__global__ __launch_bounds__(32, 12) void caps_warp_kernel(
    const float* __restrict__ x,     // (2, 32, 32, 512)
    const float* __restrict__ w,     // (288, 32, 4, 4)
    float* __restrict__ out)         // (2, 15, 15, 512)
{
    const int bid = blockIdx.x;
    const int j   = bid & 31;
    const int n   = bid >> 5;
    const int b   = n / (OH * OW);
    const int rem = n % (OH * OW);
    const int oy  = rem / OW;
    const int ox  = rem % OW;

    const int lane = threadIdx.x;    // = a (input capsule type)

    // Thread owns i_c = c*32 + lane, c = ky*3 + kx.
    const float* xbase = x + ((size_t)((b * 32 + oy * STRIDE) * 32
                                       + ox * STRIDE) * 512 + lane * PSIZE);
    const float* wbase = w + ((size_t)(lane * CAP_B) + j) * PSIZE;

    // v stored as half2: v_h2[c][q2] = (v[c][2q2], v[c][2q2+1]).
    __half2 v_h2[CPT][8];
    float t[16];                         // iter-0 pool accumulated in fp32, exact
#pragma unroll
    for (int q = 0; q < 16; q++) t[q] = 0.f;

#pragma unroll
    for (int c = 0; c < CPT; c++) {
        const int ky = c / 3, kx = c % 3;
        const float* xp = xbase + (size_t)(ky * 32 + kx) * 512;
        const float* wp = wbase + (size_t)c * 32 * CAP_B * PSIZE;
        float xm[16], wm[16];
#pragma unroll
        for (int t4 = 0; t4 < 4; t4++) {
            reinterpret_cast<float4*>(xm)[t4] = reinterpret_cast<const float4*>(xp)[t4];
            reinterpret_cast<float4*>(wm)[t4] = reinterpret_cast<const float4*>(wp)[t4];
        }
        float vv[16];
#pragma unroll
        for (int p = 0; p < 4; p++)
#pragma unroll
            for (int q = 0; q < 4; q++) {
                float acc = 0.f;
#pragma unroll
                for (int r = 0; r < 4; r++)
                    acc = fmaf(xm[p * 4 + r], wm[r * 4 + q], acc);
                vv[p * 4 + q] = acc;
                t[p * 4 + q] += acc;     // iter-0 pool, pre-rounding
            }
#pragma unroll
        for (int q2 = 0; q2 < 8; q2++)
            v_h2[c][q2] = __floats2half2_rn(vv[2 * q2], vv[2 * q2 + 1]);
    }

    float logit[CPT];
#pragma unroll
    for (int c = 0; c < CPT; c++) logit[c] = 0.f;

    float pval;   // component (lane&15) of current p

    // ---- iteration 0: r = 1/288 exactly ----
    vec_reduce16(t, lane);
    pval = squash16(t[0] * (1.0f / (float)KKA));

    // agreement: logit_c += v_c . p
#pragma unroll
    for (int q2 = 0; q2 < 8; q2++) {
        const float px = __shfl_sync(FULL, pval, 2 * q2);
        const float py = __shfl_sync(FULL, pval, 2 * q2 + 1);
#pragma unroll
        for (int c = 0; c < CPT; c++) {
            const float2 f = __half22float2(v_h2[c][q2]);
            logit[c] = fmaf(f.x, px, fmaf(f.y, py, logit[c]));
        }
    }

    // ---- iterations 1..2 ----
#pragma unroll
    for (int it = 1; it < 3; it++) {
        // softmax over all 288 logits (9 per thread, warp-reduced)
        float m = logit[0];
#pragma unroll
        for (int c = 1; c < CPT; c++) m = fmaxf(m, logit[c]);
#pragma unroll
        for (int off = 16; off >= 1; off >>= 1)
            m = fmaxf(m, __shfl_xor_sync(FULL, m, off));
        float e[CPT], z = 0.f;
#pragma unroll
        for (int c = 0; c < CPT; c++) { e[c] = __expf(logit[c] - m); z += e[c]; }
#pragma unroll
        for (int off = 16; off >= 1; off >>= 1)
            z += __shfl_xor_sync(FULL, z, off);
        const float rZ = __frcp_rn(z);

        // pool with weights e_c (fp32 accumulate), scale by 1/Z afterwards
#pragma unroll
        for (int q2 = 0; q2 < 8; q2++) {
            float ax = 0.f, ay = 0.f;
#pragma unroll
            for (int c = 0; c < CPT; c++) {
                const float2 f = __half22float2(v_h2[c][q2]);
                ax = fmaf(e[c], f.x, ax);
                ay = fmaf(e[c], f.y, ay);
            }
            t[2 * q2]     = ax;
            t[2 * q2 + 1] = ay;
        }
        vec_reduce16(t, lane);
        pval = squash16(t[0] * rZ);

        if (it < 2) {
#pragma unroll
            for (int q2 = 0; q2 < 8; q2++) {
                const float px = __shfl_sync(FULL, pval, 2 * q2);
                const float py = __shfl_sync(FULL, pval, 2 * q2 + 1);
#pragma unroll
                for (int c = 0; c < CPT; c++) {
                    const float2 f = __half22float2(v_h2[c][q2]);
                    logit[c] = fmaf(f.x, px, fmaf(f.y, py, logit[c]));
                }
            }
        }
    }

    // ---- output: lanes 0..15 hold p[0..15] ----
    if (lane < 16)
        out[(size_t)n * (CAP_B * PSIZE) + j * PSIZE + lane] = pval;
}

extern "C" void kernel_launch(void* const* d_in, const int* in_sizes, int n_in,
                              void* d_out, int out_size) {
    (void)in_sizes; (void)n_in; (void)out_size;
    const float* x = (const float*)d_in[0];
    const float* w = (const float*)d_in[1];
    float* out = (float*)d_out;

    dim3 grid(NPOS * CAP_B);   // 14400 warps, one per (n, j)
    dim3 block(32);
    caps_warp_kernel<<<grid, block>>>(x, w, out);
}

// round 7
// speedup vs baseline: 1.4458x; 1.3680x over previous
#include <cuda_runtime.h>

// Problem constants
#define CAP_A   32
#define CAP_B   32
#define KK      3
#define PSIZE   16
#define STRIDE  2
#define OH      15
#define OW      15
#define NBATCH  2
#define NPOS    (NBATCH*OH*OW)   // 450
#define KKA     (KK*KK*CAP_A)    // 288
#define EPS_SQ  1e-8f
#define CPT     9                // capsules per thread (one warp per (n,j))
#define FULL    0xffffffffu

// Transposed weights: w_t[j][i][16], i = c*32 + a  (590 KB device global)
__device__ float w_t[CAP_B * KKA * PSIZE];

// w (i, j, 16) -> w_t (j, i, 16). 36864 float4 moves; read-coalesced.
__global__ void transpose_w_kernel(const float* __restrict__ w) {
    const int f = blockIdx.x * blockDim.x + threadIdx.x;   // float4 index
    const int q4 = f & 3;
    const int j  = (f >> 2) & 31;
    const int i  = f >> 7;
    const float4 val = reinterpret_cast<const float4*>(w)[f];
    reinterpret_cast<float4*>(w_t)[(j * KKA + i) * 4 + q4] = val;
}

// Butterfly vector-exchange reduction: 32 lanes each hold t[0..15];
// afterwards lane l holds the lane-sum of component (l & 15). 31 shuffles.
__device__ __forceinline__ void vec_reduce16(float t[16], int lane) {
#pragma unroll
    for (int k = 0; k < 16; k++)
        t[k] += __shfl_xor_sync(FULL, t[k], 16);
    {
        const bool hi = lane & 8;
#pragma unroll
        for (int k = 0; k < 8; k++) {
            float keep = hi ? t[k + 8] : t[k];
            float send = hi ? t[k]     : t[k + 8];
            t[k] = keep + __shfl_xor_sync(FULL, send, 8);
        }
    }
    {
        const bool hi = lane & 4;
#pragma unroll
        for (int k = 0; k < 4; k++) {
            float keep = hi ? t[k + 4] : t[k];
            float send = hi ? t[k]     : t[k + 4];
            t[k] = keep + __shfl_xor_sync(FULL, send, 4);
        }
    }
    {
        const bool hi = lane & 2;
#pragma unroll
        for (int k = 0; k < 2; k++) {
            float keep = hi ? t[k + 2] : t[k];
            float send = hi ? t[k]     : t[k + 2];
            t[k] = keep + __shfl_xor_sync(FULL, send, 2);
        }
    }
    {
        const bool hi = lane & 1;
        float keep = hi ? t[1] : t[0];
        float send = hi ? t[0] : t[1];
        t[0] = keep + __shfl_xor_sync(FULL, send, 1);
    }
}

// Squash on the duplicated 16-vector (lanes l and l+16 both hold comp l&15).
__device__ __forceinline__ float squash16(float s) {
    float n2 = s * s;
#pragma unroll
    for (int off = 8; off >= 1; off >>= 1)
        n2 += __shfl_xor_sync(FULL, n2, off);
    return s * (n2 / (1.f + n2) * rsqrtf(n2 + EPS_SQ));
}

__global__ __launch_bounds__(32) void caps_warp_kernel(
    const float* __restrict__ x,     // (2, 32, 32, 512)
    float* __restrict__ out)         // (2, 15, 15, 512)
{
    const int bid = blockIdx.x;
    const int j   = bid & 31;
    const int n   = bid >> 5;
    const int b   = n / (OH * OW);
    const int rem = n % (OH * OW);
    const int oy  = rem / OW;
    const int ox  = rem % OW;

    const int lane = threadIdx.x;    // = a (input capsule type)

    // Thread owns i_c = c*32 + lane, c = ky*3 + kx.
    const float* xbase = x + ((size_t)((b * 32 + oy * STRIDE) * 32
                                       + ox * STRIDE) * 512 + lane * PSIZE);
    const float* wbase = w_t + ((size_t)j * KKA + lane) * PSIZE;   // coalesced

    float v[CPT][16];
#pragma unroll
    for (int c = 0; c < CPT; c++) {
        const int ky = c / 3, kx = c % 3;
        const float* xp = xbase + (size_t)(ky * 32 + kx) * 512;
        const float* wp = wbase + (size_t)(c * 32) * PSIZE;
        float xm[16], wm[16];
#pragma unroll
        for (int t4 = 0; t4 < 4; t4++) {
            reinterpret_cast<float4*>(xm)[t4] = reinterpret_cast<const float4*>(xp)[t4];
            reinterpret_cast<float4*>(wm)[t4] = reinterpret_cast<const float4*>(wp)[t4];
        }
#pragma unroll
        for (int p = 0; p < 4; p++)
#pragma unroll
            for (int q = 0; q < 4; q++) {
                float acc = 0.f;
#pragma unroll
                for (int r = 0; r < 4; r++)
                    acc = fmaf(xm[p * 4 + r], wm[r * 4 + q], acc);
                v[c][p * 4 + q] = acc;
            }
    }

    float logit[CPT];
#pragma unroll
    for (int c = 0; c < CPT; c++) logit[c] = 0.f;

    float t[16];
    float pval;   // component (lane&15) of current p

    // ---- iteration 0: logits all zero -> r = 1/288 exactly ----
#pragma unroll
    for (int q = 0; q < 16; q++) {
        float s = v[0][q];
#pragma unroll
        for (int c = 1; c < CPT; c++) s += v[c][q];
        t[q] = s;
    }
    vec_reduce16(t, lane);
    pval = squash16(t[0] * (1.0f / (float)KKA));

    // agreement: logit_c += v_c . p  (p broadcast via inline shuffles)
#pragma unroll
    for (int q = 0; q < 16; q++) {
        const float pq = __shfl_sync(FULL, pval, q);
#pragma unroll
        for (int c = 0; c < CPT; c++)
            logit[c] = fmaf(v[c][q], pq, logit[c]);
    }

    // ---- iterations 1..2 ----
#pragma unroll
    for (int it = 1; it < 3; it++) {
        // softmax over all 288 logits (9 per thread, warp-reduced)
        float m = logit[0];
#pragma unroll
        for (int c = 1; c < CPT; c++) m = fmaxf(m, logit[c]);
#pragma unroll
        for (int off = 16; off >= 1; off >>= 1)
            m = fmaxf(m, __shfl_xor_sync(FULL, m, off));
        float e[CPT], z = 0.f;
#pragma unroll
        for (int c = 0; c < CPT; c++) { e[c] = __expf(logit[c] - m); z += e[c]; }
#pragma unroll
        for (int off = 16; off >= 1; off >>= 1)
            z += __shfl_xor_sync(FULL, z, off);
        const float rZ = __frcp_rn(z);

        // pool with weights e_c (scale by 1/Z after the reduction)
#pragma unroll
        for (int q = 0; q < 16; q++) {
            float s = e[0] * v[0][q];
#pragma unroll
            for (int c = 1; c < CPT; c++) s = fmaf(e[c], v[c][q], s);
            t[q] = s;
        }
        vec_reduce16(t, lane);
        pval = squash16(t[0] * rZ);

        if (it < 2) {
#pragma unroll
            for (int q = 0; q < 16; q++) {
                const float pq = __shfl_sync(FULL, pval, q);
#pragma unroll
                for (int c = 0; c < CPT; c++)
                    logit[c] = fmaf(v[c][q], pq, logit[c]);
            }
        }
    }

    // ---- output: lanes 0..15 hold p[0..15] ----
    if (lane < 16)
        out[(size_t)n * (CAP_B * PSIZE) + j * PSIZE + lane] = pval;
}

extern "C" void kernel_launch(void* const* d_in, const int* in_sizes, int n_in,
                              void* d_out, int out_size) {
    (void)in_sizes; (void)n_in; (void)out_size;
    const float* x = (const float*)d_in[0];
    const float* w = (const float*)d_in[1];
    float* out = (float*)d_out;

    // 1) transpose weights into w_t (j-major, lane-coalesced)
    transpose_w_kernel<<<(KKA * CAP_B * 4) / 256, 256>>>(w);   // 144 blocks

    // 2) fused transform + routing, one warp per (n, j)
    dim3 grid(NPOS * CAP_B);   // 14400
    caps_warp_kernel<<<grid, 32>>>(x, out);
}